// round 8
// baseline (speedup 1.0000x reference)
#include <cuda_runtime.h>
#include <math.h>

#define NB    16
#define NP    32768
#define NC    81
#define CM1   80
#define NBINS 2048
#define SCAP  4096
#define RCAP  4096
#define NCAND 400
#define NOUT  100

// ---------------- scratch (static device globals; zero-initialized at load) --------
__device__ float              g_rowsc[NB * NP];
__device__ unsigned int       g_hist[NB * NBINS];   // zeroed in-kernel after use
__device__ int                g_bt[NB];             // filter bin (bt-1, both uses)
__device__ int                g_cnt[NB];            // reset in-kernel after use
__device__ unsigned int       g_done1[NB];
__device__ unsigned int       g_done2[NB];
__device__ unsigned long long g_cand[NB * SCAP];

__device__ __forceinline__ int binf(float s) {
    int b = (int)floorf((s + 30.0f) * (NBINS / 40.0f));
    b = b < 0 ? 0 : b;
    b = b > (NBINS - 1) ? (NBINS - 1) : b;
    return b;
}

__device__ __forceinline__ unsigned int okey(float s) {
    unsigned int u = __float_as_uint(s);
    return (u & 0x80000000u) ? ~u : (u | 0x80000000u);
}
__device__ __forceinline__ float unokey(unsigned int k) {
    return __uint_as_float((k & 0x80000000u) ? (k ^ 0x80000000u) : ~k);
}

// ============ K1: approx row-score + histogram; last block finds threshold ==========
__global__ void __launch_bounds__(256)
k_rowscore(const float* __restrict__ logits) {
    const int img = blockIdx.y;
    const int lane = threadIdx.x & 31;
    const int w = blockIdx.x * 8 + (threadIdx.x >> 5);   // 0..2047 per image
    const float* base = logits + (size_t)img * NP * NC;
    const bool t3 = (lane < 17);

#pragma unroll 1
    for (int it = 0; it < 2; it++) {
        const int p = w * 8 + it * 16384;                // 8 consecutive rows
        const float* r = base + (size_t)p * NC;
        float a[8], b[8], c[8];
#pragma unroll
        for (int q = 0; q < 8; q++) {                    // 24 loads batched -> MLP
            a[q] = r[q * NC + lane];
            b[q] = r[q * NC + lane + 32];
            c[q] = t3 ? r[q * NC + lane + 64] : -1e30f;
        }
        float s[8], fgm[8];
#pragma unroll
        for (int q = 0; q < 8; q++) {
            float fa = (lane == 0) ? -1e30f : a[q];      // exclude background (c=0)
            float fg = fmaxf(fmaxf(fa, b[q]), c[q]);
            fgm[q] = unokey(__reduce_max_sync(0xffffffffu, okey(fg)));
            s[q] = __expf(a[q]) + __expf(b[q]) + (t3 ? __expf(c[q]) : 0.0f);
        }
#pragma unroll
        for (int o = 16; o; o >>= 1) {
#pragma unroll
            for (int q = 0; q < 8; q++)
                s[q] += __shfl_xor_sync(0xffffffffu, s[q], o);
        }
        if (lane == 0) {
#pragma unroll
            for (int q = 0; q < 8; q++) {
                float rs = fgm[q] - __logf(s[q]);
                g_rowsc[img * NP + p + q] = rs;
                atomicAdd(&g_hist[img * NBINS + binf(rs)], 1u);
            }
        }
    }

    // ---- last-block-per-image: threshold find + hist re-zero ----
    __shared__ int slast;
    __shared__ unsigned int wsum[8];
    __shared__ int sbt;
    __syncthreads();
    __threadfence();
    if (threadIdx.x == 0)
        slast = (atomicAdd(&g_done1[img], 1u) == gridDim.x - 1);
    __syncthreads();
    if (!slast) return;
    __threadfence();

    const int t = threadIdx.x;
    const int warp = t >> 5;
    const int hi = NBINS - 1 - 8 * t;   // 8 descending bins per thread
    unsigned int v[8];
    unsigned int sum = 0;
#pragma unroll
    for (int k = 0; k < 8; k++) {
        v[k] = g_hist[img * NBINS + hi - k];
        g_hist[img * NBINS + hi - k] = 0u;   // re-zero for next replay
        sum += v[k];
    }
    unsigned int x = sum;
#pragma unroll
    for (int o = 1; o < 32; o <<= 1) {
        unsigned int y = __shfl_up_sync(0xffffffffu, x, o);
        if (lane >= o) x += y;
    }
    if (lane == 31) wsum[warp] = x;
    __syncthreads();
    if (warp == 0) {
        unsigned int tv = (lane < 8) ? wsum[lane] : 0u;
        unsigned int tx = tv;
#pragma unroll
        for (int o = 1; o < 8; o <<= 1) {
            unsigned int y = __shfl_up_sync(0xffffffffu, tx, o);
            if (lane >= o) tx += y;
        }
        if (lane < 8) wsum[lane] = tx - tv;   // exclusive warp offsets
    }
    __syncthreads();
    {
        unsigned int incl = x + wsum[warp];
        unsigned int excl = incl - sum;
        if (excl < NCAND && incl >= NCAND) {
            unsigned int cum = excl;
#pragma unroll
            for (int k = 0; k < 8; k++) {
                cum += v[k];
                if (cum >= NCAND) { sbt = hi - k; break; }
            }
        }
        if (t == 255 && incl < NCAND) sbt = 0;   // never expected
    }
    __syncthreads();
    if (t == 0) {
        int bt = sbt - 1; if (bt < 0) bt = 0;    // 1-bin margin (approx err ~1e-6)
        g_bt[img] = bt;
        g_done1[img] = 0u;                       // reset for next replay
    }
}

// ============ K2: gather + exact rescore; last block: rank-sort + NMS + output ======
struct FinalS {
    unsigned long long cand[SCAP];     // 32 KB (overlaid by rows[] in phase A/B)
    unsigned long long sorted[NCAND];  // rank-sorted top-400
    float4 obx4[NCAND];
    float bx[NCAND][4];
    float sc[NCAND];
    int   lb[NCAND];
    float area[NCAND];
    unsigned int adj[NCAND][13];
    unsigned int keepw[13];
    int   wpre[14];
    int   kidx[NOUT];
    float red[33];
};

__global__ void __launch_bounds__(1024, 1)
k_gather_final(const float* __restrict__ logits,
               const float* __restrict__ bbox,
               const float* __restrict__ priors,
               float* __restrict__ out) {
    extern __shared__ char smraw[];
    FinalS& S = *reinterpret_cast<FinalS*>(smraw);
    int* rows = reinterpret_cast<int*>(smraw);       // overlays S.cand (phase A/B only)
    __shared__ int snr;
    __shared__ int slast;

    const int img = blockIdx.y;
    const int tid = threadIdx.x;
    const int lane = tid & 31;
    const int warp = tid >> 5;
    const int bt = g_bt[img];

    if (tid == 0) snr = 0;
    __syncthreads();

    // ---- phase A: scan this block's 4096 rows of approx scores (1 float4/thread) ----
    {
        const float4* rsc4 = (const float4*)(g_rowsc + (size_t)img * NP) + blockIdx.x * 1024;
        float4 v = rsc4[tid];
        int br = blockIdx.x * 4096 + tid * 4;
        if (binf(v.x) >= bt) { int q = atomicAdd(&snr, 1); if (q < RCAP) rows[q] = br; }
        if (binf(v.y) >= bt) { int q = atomicAdd(&snr, 1); if (q < RCAP) rows[q] = br + 1; }
        if (binf(v.z) >= bt) { int q = atomicAdd(&snr, 1); if (q < RCAP) rows[q] = br + 2; }
        if (binf(v.w) >= bt) { int q = atomicAdd(&snr, 1); if (q < RCAP) rows[q] = br + 3; }
    }
    __syncthreads();

    // ---- phase B: exact rescoring (warp per row) -> push candidates to global ----
    {
        int n = snr < RCAP ? snr : RCAP;
        for (int ri = warp; ri < n; ri += 32) {
            int p = rows[ri];
            const float* row = logits + ((size_t)img * NP + p) * NC;
            float a = row[lane];
            float b = row[lane + 32];
            float c = (lane < 17) ? row[lane + 64] : -INFINITY;
            float m = fmaxf(fmaxf(a, b), c);
#pragma unroll
            for (int o = 16; o; o >>= 1) m = fmaxf(m, __shfl_xor_sync(0xffffffffu, m, o));
            float sv = expf(a - m) + expf(b - m);
            if (lane < 17) sv += expf(c - m);
#pragma unroll
            for (int o = 16; o; o >>= 1) sv += __shfl_xor_sync(0xffffffffu, sv, o);
            float logs = logf(sv);
#pragma unroll
            for (int k = 0; k < 3; k++) {
                int cc = lane + 32 * k;
                float xv = (k == 0) ? a : (k == 1) ? b : c;
                if (cc >= 1 && cc < NC) {
                    float scv = (xv - m) - logs;
                    if (binf(scv) >= bt) {
                        int pos = atomicAdd(&g_cnt[img], 1);
                        if (pos < SCAP) {
                            unsigned int flat = (unsigned int)(p * CM1 + (cc - 1));
                            g_cand[img * SCAP + pos] =
                                ((unsigned long long)okey(scv) << 32) | (unsigned int)(~flat);
                        }
                    }
                }
            }
        }
    }

    // ---- handshake: last block of this image proceeds to the finale ----
    __syncthreads();
    __threadfence();
    if (tid == 0)
        slast = (atomicAdd(&g_done2[img], 1u) == gridDim.x - 1);
    __syncthreads();
    if (!slast) return;
    __threadfence();

    // =================== FINALE (16 blocks, one per image) ===================
    int n = g_cnt[img];
    if (n > SCAP) n = SCAP;
    for (int i = tid; i < n; i += 1024) S.cand[i] = g_cand[img * SCAP + i];
    if (tid < NCAND) S.sorted[tid] = 0ull;
    __syncthreads();

    // barrier-free rank sort: rank_i = #{j : key_j > key_i}; keep rank < 400
    for (int base = 0; base < n; base += 1024) {
        int i = base + tid;
        unsigned long long mine = (i < n) ? S.cand[i] : 0ull;
        int rank = 0;
#pragma unroll 4
        for (int j = 0; j < n; j++)
            rank += (S.cand[j] > mine);          // broadcast LDS, conflict-free
        if (i < n && rank < NCAND) S.sorted[rank] = mine;
    }
    __syncthreads();

    // top-400 unpack + box decode
    if (tid < NCAND) {
        int r = tid;
        unsigned long long v = S.sorted[r];
        float score = unokey((unsigned int)(v >> 32));
        int flat = (int)(~(unsigned int)(v & 0xffffffffu));
        int p = flat / CM1;
        int lbl = flat - p * CM1 + 1;
        const float* loc = bbox + ((size_t)img * NP + p) * 4;
        float px = priors[p * 4 + 0], py = priors[p * 4 + 1];
        float pw = priors[p * 4 + 2], ph = priors[p * 4 + 3];
        float cx = loc[0] * 0.1f * pw + px;
        float cy = loc[1] * 0.1f * ph + py;
        float w = expf(loc[2] * 0.2f) * pw;
        float h = expf(loc[3] * 0.2f) * ph;
        S.bx[r][0] = (cx - w * 0.5f) * 512.0f;
        S.bx[r][1] = (cy - h * 0.5f) * 512.0f;
        S.bx[r][2] = (cx + w * 0.5f) * 512.0f;
        S.bx[r][3] = (cy + h * 0.5f) * 512.0f;
        S.sc[r] = score;
        S.lb[r] = lbl;
    }
    __syncthreads();

    // max over all coords: two-level warp reduce
    {
        float mx = -INFINITY;
        for (int i = tid; i < NCAND * 4; i += 1024) mx = fmaxf(mx, ((float*)S.bx)[i]);
#pragma unroll
        for (int o = 16; o; o >>= 1) mx = fmaxf(mx, __shfl_xor_sync(0xffffffffu, mx, o));
        if (lane == 0) S.red[warp] = mx;
        __syncthreads();
        if (warp == 0) {
            float v = S.red[lane];
#pragma unroll
            for (int o = 16; o; o >>= 1) v = fmaxf(v, __shfl_xor_sync(0xffffffffu, v, o));
            if (lane == 0) S.red[32] = v;
        }
        __syncthreads();
    }
    float maxc = S.red[32];

    // class-offset boxes + areas (on offset boxes, matching reference rounding)
    if (tid < NCAND) {
        int r = tid;
        float off = (float)S.lb[r] * (maxc + 1.0f);
        float x1 = S.bx[r][0] + off, y1 = S.bx[r][1] + off;
        float x2 = S.bx[r][2] + off, y2 = S.bx[r][3] + off;
        S.obx4[r] = make_float4(x1, y1, x2, y2);
        S.area[r] = (x2 - x1) * (y2 - y1);
    }
    __syncthreads();

    // adjacency bitmatrix, words w >= i>>5 only
    for (int i = warp; i < NCAND; i += 32) {
        float4 bi = S.obx4[i];
        float ai = S.area[i];
        for (int w = i >> 5; w < 13; w++) {
            int j = w * 32 + lane;
            bool pred = false;
            if (j < NCAND && j > i) {
                float4 bj = S.obx4[j];
                float lt0 = fmaxf(bi.x, bj.x);
                float lt1 = fmaxf(bi.y, bj.y);
                float rb0 = fminf(bi.z, bj.z);
                float rb1 = fminf(bi.w, bj.w);
                float ww = fmaxf(rb0 - lt0, 0.0f);
                float hh = fmaxf(rb1 - lt1, 0.0f);
                float inter = ww * hh;
                float uni = ai + S.area[j] - inter;
                pred = (inter / fmaxf(uni, 1e-12f)) > 0.45f;
            }
            unsigned int bits = __ballot_sync(0xffffffffu, pred);
            if (lane == 0) S.adj[i][w] = bits;
        }
    }
    __syncthreads();

    // greedy NMS on warp 0 (13 keep-words, prefetched rows)
    if (tid < 32) {
        unsigned int kw;
        if (lane < 12) kw = 0xffffffffu;
        else if (lane == 12) kw = 0x0000ffffu;
        else kw = 0u;
        unsigned int nextrow = (lane < 13) ? S.adj[0][lane] : 0u;
        for (int i = 0; i < NCAND; i++) {
            unsigned int row = nextrow;
            nextrow = (lane < 13 && lane >= ((i + 1) >> 5) && i + 1 < NCAND)
                          ? S.adj[i + 1][lane] : 0u;
            unsigned int w = __shfl_sync(0xffffffffu, kw, i >> 5);
            if ((w >> (i & 31)) & 1u) kw &= ~row;
        }
        if (lane < 13) S.keepw[lane] = kw;
    }
    __syncthreads();

    // parallel rank select + output
    if (tid == 0) {
        int sacc = 0;
#pragma unroll
        for (int w = 0; w < 13; w++) { S.wpre[w] = sacc; sacc += __popc(S.keepw[w]); }
        S.wpre[13] = sacc;
    }
    __syncthreads();
    int K = S.wpre[13];
    if (tid < NCAND) {
        int i = tid;
        unsigned int word = S.keepw[i >> 5];
        unsigned int below = word & ((1u << (i & 31)) - 1u);
        int kb = S.wpre[i >> 5] + __popc(below);
        if ((word >> (i & 31)) & 1u) {
            if (kb < NOUT) S.kidx[kb] = i;
        } else {
            int nr2 = i - kb;
            if (K + nr2 < NOUT) S.kidx[K + nr2] = i;
        }
    }
    __syncthreads();

    if (tid < NOUT) {
        int r = tid;
        int i = S.kidx[r];
        bool kept = (S.keepw[i >> 5] >> (i & 31)) & 1u;
        float* ob = out + ((size_t)img * NOUT + r) * 4;
        ob[0] = S.bx[i][0]; ob[1] = S.bx[i][1]; ob[2] = S.bx[i][2]; ob[3] = S.bx[i][3];
        out[NB * NOUT * 4 + img * NOUT + r] = (float)S.lb[i];
        out[NB * NOUT * 5 + img * NOUT + r] = kept ? S.sc[i] : -INFINITY;
    }
    if (tid == 0) {                        // reset for next graph replay
        g_cnt[img] = 0;
        g_done2[img] = 0u;
    }
}

// ---------------- launch ----------------
extern "C" void kernel_launch(void* const* d_in, const int* in_sizes, int n_in,
                              void* d_out, int out_size) {
    const float* logits = (const float*)d_in[0];
    const float* bbox   = (const float*)d_in[1];
    const float* priors = (const float*)d_in[2];
    float* out = (float*)d_out;

    k_rowscore<<<dim3(256, NB), 256>>>(logits);
    cudaFuncSetAttribute(k_gather_final, cudaFuncAttributeMaxDynamicSharedMemorySize,
                         (int)sizeof(FinalS));
    k_gather_final<<<dim3(8, NB), 1024, sizeof(FinalS)>>>(logits, bbox, priors, out);
}

// round 9
// speedup vs baseline: 1.1309x; 1.1309x over previous
#include <cuda_runtime.h>
#include <math.h>

#define NB    16
#define NP    32768
#define NC    81
#define CM1   80
#define NBINS 2048
#define SCAP  4096
#define RCAP  4096
#define NCAND 400
#define NOUT  100

#define K1_BLK   512
#define K1_GX    16
#define ROWS_STG 64
#define STG_F    (ROWS_STG * NC)        // 5184 floats per stage
#define STG_V    (STG_F / 4)            // 1296 float4 per stage

// ---------------- scratch (static device globals; zero-initialized at load) --------
__device__ float              g_rowsc[NB * NP];
__device__ unsigned int       g_hist[NB * NBINS];   // zeroed in-kernel after use
__device__ int                g_btr[NB];            // row filter bin   (sbt-2)
__device__ int                g_bte[NB];            // element filter bin (sbt-1)
__device__ int                g_cnt[NB];
__device__ unsigned int       g_done1[NB];
__device__ unsigned int       g_done2[NB];
__device__ unsigned long long g_cand[NB * SCAP];

__device__ __forceinline__ int binf(float s) {
    int b = (int)floorf((s + 30.0f) * (NBINS / 40.0f));
    b = b < 0 ? 0 : b;
    b = b > (NBINS - 1) ? (NBINS - 1) : b;
    return b;
}
__device__ __forceinline__ unsigned int okey(float s) {
    unsigned int u = __float_as_uint(s);
    return (u & 0x80000000u) ? ~u : (u | 0x80000000u);
}
__device__ __forceinline__ float unokey(unsigned int k) {
    return __uint_as_float((k & 0x80000000u) ? (k ^ 0x80000000u) : ~k);
}

// ============ K1: cp.async-staged approx row-score + histogram + threshold ==========
__global__ void __launch_bounds__(K1_BLK)
k_rowscore(const float* __restrict__ logits) {
    __shared__ float sbuf[2][STG_F];
    const int img = blockIdx.y;
    const int tid = threadIdx.x;
    const int lane = tid & 31;
    const int warp = tid >> 5;                       // 0..15
    const bool t3 = (lane < 17);
    const int rows_blk = NP / K1_GX;                 // 2048
    const int nstg = rows_blk / ROWS_STG;            // 32
    const float* gsrc = logits + (size_t)img * NP * NC + (size_t)blockIdx.x * rows_blk * NC;

    // stage loader: 16B cp.async, fully coalesced (stage is contiguous in gmem)
    auto stage_load = [&](int s, int buf) {
        const float4* src = (const float4*)(gsrc + (size_t)s * STG_F);
        unsigned int dst = (unsigned int)__cvta_generic_to_shared(&sbuf[buf][0]);
#pragma unroll
        for (int k = 0; k < 3; k++) {
            int idx = tid + k * K1_BLK;
            if (idx < STG_V)
                asm volatile("cp.async.cg.shared.global [%0], [%1], 16;\n"
                             :: "r"(dst + idx * 16), "l"(src + idx));
        }
        asm volatile("cp.async.commit_group;\n" ::);
    };

    stage_load(0, 0);
    stage_load(1, 1);

    for (int s = 0; s < nstg; s++) {
        asm volatile("cp.async.wait_group 1;\n" ::);   // stage s complete (s+1 may fly)
        __syncthreads();
        const float* sb = sbuf[s & 1];
#pragma unroll
        for (int q = 0; q < 4; q++) {
            int r = warp * 4 + q;                      // row within stage
            const float* row = sb + r * NC;
            float a = row[lane];
            float b = row[lane + 32];
            float c = t3 ? row[lane + 64] : -1e30f;
            float fa = (lane == 0) ? -1e30f : a;       // exclude background (c=0)
            float fg = fmaxf(fmaxf(fa, b), c);
            fg = unokey(__reduce_max_sync(0xffffffffu, okey(fg)));
            float sv = __expf(a) + __expf(b) + (t3 ? __expf(c) : 0.0f);
#pragma unroll
            for (int o = 16; o; o >>= 1) sv += __shfl_xor_sync(0xffffffffu, sv, o);
            if (lane == 0) {
                float rs = fg - __logf(sv);
                int p = blockIdx.x * rows_blk + s * ROWS_STG + r;
                g_rowsc[img * NP + p] = rs;
                atomicAdd(&g_hist[img * NBINS + binf(rs)], 1u);
            }
        }
        __syncthreads();                               // all done reading sbuf[s&1]
        if (s + 2 < nstg) stage_load(s + 2, s & 1);
        else asm volatile("cp.async.commit_group;\n" ::);   // keep group-count invariant
    }

    // ---- last-block-per-image: threshold find + hist re-zero ----
    __shared__ int slast;
    __shared__ unsigned int wsum[16];
    __shared__ int sbt;
    __syncthreads();
    __threadfence();
    if (tid == 0)
        slast = (atomicAdd(&g_done1[img], 1u) == gridDim.x - 1);
    __syncthreads();
    if (!slast) return;
    __threadfence();

    const int hi = NBINS - 1 - 4 * tid;               // 4 descending bins per thread
    unsigned int v[4];
    unsigned int sum = 0;
#pragma unroll
    for (int k = 0; k < 4; k++) {
        v[k] = g_hist[img * NBINS + hi - k];
        g_hist[img * NBINS + hi - k] = 0u;            // re-zero for next replay
        sum += v[k];
    }
    unsigned int x = sum;
#pragma unroll
    for (int o = 1; o < 32; o <<= 1) {
        unsigned int y = __shfl_up_sync(0xffffffffu, x, o);
        if (lane >= o) x += y;
    }
    if (lane == 31) wsum[warp] = x;
    __syncthreads();
    if (warp == 0) {
        unsigned int tv = (lane < 16) ? wsum[lane] : 0u;
        unsigned int tx = tv;
#pragma unroll
        for (int o = 1; o < 16; o <<= 1) {
            unsigned int y = __shfl_up_sync(0xffffffffu, tx, o);
            if (lane >= o) tx += y;
        }
        if (lane < 16) wsum[lane] = tx - tv;          // exclusive warp offsets
    }
    __syncthreads();
    {
        unsigned int incl = x + wsum[warp];
        unsigned int excl = incl - sum;
        if (excl < NCAND && incl >= NCAND) {
            unsigned int cum = excl;
#pragma unroll
            for (int k = 0; k < 4; k++) {
                cum += v[k];
                if (cum >= NCAND) { sbt = hi - k; break; }
            }
        }
        if (tid == K1_BLK - 1 && incl < NCAND) sbt = 0;   // never expected
    }
    __syncthreads();
    if (tid == 0) {
        int be = sbt - 1; if (be < 0) be = 0;
        int br = sbt - 2; if (br < 0) br = 0;
        g_bte[img] = be;
        g_btr[img] = br;
        g_done1[img] = 0u;
    }
}

// ============ K2: gather + exact rescore; last block: bitonic + NMS + output ========
struct FinalS {
    unsigned long long cand[SCAP];     // 32 KB (overlaid by rows[] in phase A/B)
    float4 obx4[NCAND];
    float bx[NCAND][4];
    float sc[NCAND];
    int   lb[NCAND];
    float area[NCAND];
    unsigned int adj[NCAND][13];
    unsigned int keepw[13];
    int   wpre[14];
    int   kidx[NOUT];
    float red[33];
};

__global__ void __launch_bounds__(1024, 1)
k_gather_final(const float* __restrict__ logits,
               const float* __restrict__ bbox,
               const float* __restrict__ priors,
               float* __restrict__ out) {
    extern __shared__ char smraw[];
    FinalS& S = *reinterpret_cast<FinalS*>(smraw);
    int* rows = reinterpret_cast<int*>(smraw);       // overlays S.cand (phase A/B only)
    __shared__ int snr;
    __shared__ int slast;

    const int img = blockIdx.y;
    const int tid = threadIdx.x;
    const int lane = tid & 31;
    const int warp = tid >> 5;
    const int btr = g_btr[img];
    const int bte = g_bte[img];

    if (tid == 0) snr = 0;
    __syncthreads();

    // ---- phase A: scan this block's 4096 rows of approx scores ----
    {
        const float4* rsc4 = (const float4*)(g_rowsc + (size_t)img * NP) + blockIdx.x * 1024;
        float4 v = rsc4[tid];
        int br = blockIdx.x * 4096 + tid * 4;
        if (binf(v.x) >= btr) { int q = atomicAdd(&snr, 1); if (q < RCAP) rows[q] = br; }
        if (binf(v.y) >= btr) { int q = atomicAdd(&snr, 1); if (q < RCAP) rows[q] = br + 1; }
        if (binf(v.z) >= btr) { int q = atomicAdd(&snr, 1); if (q < RCAP) rows[q] = br + 2; }
        if (binf(v.w) >= btr) { int q = atomicAdd(&snr, 1); if (q < RCAP) rows[q] = br + 3; }
    }
    __syncthreads();

    // ---- phase B: exact rescoring (warp per row) -> push candidates to global ----
    {
        int n = snr < RCAP ? snr : RCAP;
        for (int ri = warp; ri < n; ri += 32) {
            int p = rows[ri];
            const float* row = logits + ((size_t)img * NP + p) * NC;
            float a = row[lane];
            float b = row[lane + 32];
            float c = (lane < 17) ? row[lane + 64] : -INFINITY;
            float m = fmaxf(fmaxf(a, b), c);
#pragma unroll
            for (int o = 16; o; o >>= 1) m = fmaxf(m, __shfl_xor_sync(0xffffffffu, m, o));
            float sv = expf(a - m) + expf(b - m);
            if (lane < 17) sv += expf(c - m);
#pragma unroll
            for (int o = 16; o; o >>= 1) sv += __shfl_xor_sync(0xffffffffu, sv, o);
            float logs = logf(sv);
#pragma unroll
            for (int k = 0; k < 3; k++) {
                int cc = lane + 32 * k;
                float xv = (k == 0) ? a : (k == 1) ? b : c;
                if (cc >= 1 && cc < NC) {
                    float scv = (xv - m) - logs;
                    if (binf(scv) >= bte) {
                        int pos = atomicAdd(&g_cnt[img], 1);
                        if (pos < SCAP) {
                            unsigned int flat = (unsigned int)(p * CM1 + (cc - 1));
                            g_cand[img * SCAP + pos] =
                                ((unsigned long long)okey(scv) << 32) | (unsigned int)(~flat);
                        }
                    }
                }
            }
        }
    }

    // ---- handshake: last block of this image proceeds to the finale ----
    __syncthreads();
    __threadfence();
    if (tid == 0)
        slast = (atomicAdd(&g_done2[img], 1u) == gridDim.x - 1);
    __syncthreads();
    if (!slast) return;
    __threadfence();

    // =================== FINALE (16 blocks, one per image) ===================
    int n = g_cnt[img];
    if (n > SCAP) n = SCAP;
    for (int i = tid; i < n; i += 1024) S.cand[i] = g_cand[img * SCAP + i];
    int M = 512;
    while (M < n) M <<= 1;
    for (int i = tid; i < M; i += 1024)
        if (i >= n) S.cand[i] = 0ull;
    __syncthreads();

    // bitonic sort descending on packed (key, ~idx)
    for (int k = 2; k <= M; k <<= 1) {
        for (int j = k >> 1; j > 0; j >>= 1) {
            for (int i = tid; i < M; i += 1024) {
                int ixj = i ^ j;
                if (ixj > i) {
                    unsigned long long a = S.cand[i], b = S.cand[ixj];
                    bool sw = ((i & k) == 0) ? (a < b) : (a > b);
                    if (sw) { S.cand[i] = b; S.cand[ixj] = a; }
                }
            }
            __syncthreads();
        }
    }

    // top-400 unpack + box decode
    if (tid < NCAND) {
        int r = tid;
        unsigned long long v = S.cand[r];
        float score = unokey((unsigned int)(v >> 32));
        int flat = (int)(~(unsigned int)(v & 0xffffffffu));
        int p = flat / CM1;
        int lbl = flat - p * CM1 + 1;
        const float* loc = bbox + ((size_t)img * NP + p) * 4;
        float px = priors[p * 4 + 0], py = priors[p * 4 + 1];
        float pw = priors[p * 4 + 2], ph = priors[p * 4 + 3];
        float cx = loc[0] * 0.1f * pw + px;
        float cy = loc[1] * 0.1f * ph + py;
        float w = expf(loc[2] * 0.2f) * pw;
        float h = expf(loc[3] * 0.2f) * ph;
        S.bx[r][0] = (cx - w * 0.5f) * 512.0f;
        S.bx[r][1] = (cy - h * 0.5f) * 512.0f;
        S.bx[r][2] = (cx + w * 0.5f) * 512.0f;
        S.bx[r][3] = (cy + h * 0.5f) * 512.0f;
        S.sc[r] = score;
        S.lb[r] = lbl;
    }
    __syncthreads();

    // max over all coords: two-level warp reduce
    {
        float mx = -INFINITY;
        for (int i = tid; i < NCAND * 4; i += 1024) mx = fmaxf(mx, ((float*)S.bx)[i]);
#pragma unroll
        for (int o = 16; o; o >>= 1) mx = fmaxf(mx, __shfl_xor_sync(0xffffffffu, mx, o));
        if (lane == 0) S.red[warp] = mx;
        __syncthreads();
        if (warp == 0) {
            float v = S.red[lane];
#pragma unroll
            for (int o = 16; o; o >>= 1) v = fmaxf(v, __shfl_xor_sync(0xffffffffu, v, o));
            if (lane == 0) S.red[32] = v;
        }
        __syncthreads();
    }
    float maxc = S.red[32];

    // class-offset boxes + areas (on offset boxes, matching reference rounding)
    if (tid < NCAND) {
        int r = tid;
        float off = (float)S.lb[r] * (maxc + 1.0f);
        float x1 = S.bx[r][0] + off, y1 = S.bx[r][1] + off;
        float x2 = S.bx[r][2] + off, y2 = S.bx[r][3] + off;
        S.obx4[r] = make_float4(x1, y1, x2, y2);
        S.area[r] = (x2 - x1) * (y2 - y1);
    }
    __syncthreads();

    // adjacency bitmatrix, words w >= i>>5 only
    for (int i = warp; i < NCAND; i += 32) {
        float4 bi = S.obx4[i];
        float ai = S.area[i];
        for (int w = i >> 5; w < 13; w++) {
            int j = w * 32 + lane;
            bool pred = false;
            if (j < NCAND && j > i) {
                float4 bj = S.obx4[j];
                float lt0 = fmaxf(bi.x, bj.x);
                float lt1 = fmaxf(bi.y, bj.y);
                float rb0 = fminf(bi.z, bj.z);
                float rb1 = fminf(bi.w, bj.w);
                float ww = fmaxf(rb0 - lt0, 0.0f);
                float hh = fmaxf(rb1 - lt1, 0.0f);
                float inter = ww * hh;
                float uni = ai + S.area[j] - inter;
                pred = (inter / fmaxf(uni, 1e-12f)) > 0.45f;
            }
            unsigned int bits = __ballot_sync(0xffffffffu, pred);
            if (lane == 0) S.adj[i][w] = bits;
        }
    }
    __syncthreads();

    // greedy NMS on warp 0 (13 keep-words, prefetched rows)
    if (tid < 32) {
        unsigned int kw;
        if (lane < 12) kw = 0xffffffffu;
        else if (lane == 12) kw = 0x0000ffffu;
        else kw = 0u;
        unsigned int nextrow = (lane < 13) ? S.adj[0][lane] : 0u;
        for (int i = 0; i < NCAND; i++) {
            unsigned int row = nextrow;
            nextrow = (lane < 13 && lane >= ((i + 1) >> 5) && i + 1 < NCAND)
                          ? S.adj[i + 1][lane] : 0u;
            unsigned int w = __shfl_sync(0xffffffffu, kw, i >> 5);
            if ((w >> (i & 31)) & 1u) kw &= ~row;
        }
        if (lane < 13) S.keepw[lane] = kw;
    }
    __syncthreads();

    // parallel rank select + output
    if (tid == 0) {
        int sacc = 0;
#pragma unroll
        for (int w = 0; w < 13; w++) { S.wpre[w] = sacc; sacc += __popc(S.keepw[w]); }
        S.wpre[13] = sacc;
    }
    __syncthreads();
    int K = S.wpre[13];
    if (tid < NCAND) {
        int i = tid;
        unsigned int word = S.keepw[i >> 5];
        unsigned int below = word & ((1u << (i & 31)) - 1u);
        int kb = S.wpre[i >> 5] + __popc(below);
        if ((word >> (i & 31)) & 1u) {
            if (kb < NOUT) S.kidx[kb] = i;
        } else {
            int nr2 = i - kb;
            if (K + nr2 < NOUT) S.kidx[K + nr2] = i;
        }
    }
    __syncthreads();

    if (tid < NOUT) {
        int r = tid;
        int i = S.kidx[r];
        bool kept = (S.keepw[i >> 5] >> (i & 31)) & 1u;
        float* ob = out + ((size_t)img * NOUT + r) * 4;
        ob[0] = S.bx[i][0]; ob[1] = S.bx[i][1]; ob[2] = S.bx[i][2]; ob[3] = S.bx[i][3];
        out[NB * NOUT * 4 + img * NOUT + r] = (float)S.lb[i];
        out[NB * NOUT * 5 + img * NOUT + r] = kept ? S.sc[i] : -INFINITY;
    }
    if (tid == 0) {                        // reset for next graph replay
        g_cnt[img] = 0;
        g_done2[img] = 0u;
    }
}

// ---------------- launch ----------------
extern "C" void kernel_launch(void* const* d_in, const int* in_sizes, int n_in,
                              void* d_out, int out_size) {
    const float* logits = (const float*)d_in[0];
    const float* bbox   = (const float*)d_in[1];
    const float* priors = (const float*)d_in[2];
    float* out = (float*)d_out;

    k_rowscore<<<dim3(K1_GX, NB), K1_BLK>>>(logits);
    cudaFuncSetAttribute(k_gather_final, cudaFuncAttributeMaxDynamicSharedMemorySize,
                         (int)sizeof(FinalS));
    k_gather_final<<<dim3(8, NB), 1024, sizeof(FinalS)>>>(logits, bbox, priors, out);
}

// round 10
// speedup vs baseline: 1.3051x; 1.1541x over previous
#include <cuda_runtime.h>
#include <math.h>

#define NB    16
#define NP    32768
#define NC    81
#define CM1   80
#define NBINS 2048
#define SCAP  4096
#define NCAND 400
#define NOUT  100

#define K1_BLK   512
#define K1_GX    16
#define ROWS_STG 64
#define STG_F    (ROWS_STG * NC)        // 5184 floats per stage
#define STG_V    (STG_F / 4)            // 1296 float4 per stage

// ---------------- scratch (static device globals; zero-initialized at load) --------
__device__ float              g_rowsc[NB * NP];
__device__ unsigned int       g_hist[NB * NBINS];   // zeroed in-kernel after use
__device__ int                g_btr[NB];            // row filter bin   (sbt-2)
__device__ int                g_bte[NB];            // element filter bin (sbt-1)
__device__ int                g_cnt[NB];            // reset by K3
__device__ unsigned int       g_done1[NB];
__device__ unsigned long long g_cand[NB * SCAP];

__device__ __forceinline__ int binf(float s) {
    int b = (int)floorf((s + 30.0f) * (NBINS / 40.0f));
    b = b < 0 ? 0 : b;
    b = b > (NBINS - 1) ? (NBINS - 1) : b;
    return b;
}
__device__ __forceinline__ unsigned int okey(float s) {
    unsigned int u = __float_as_uint(s);
    return (u & 0x80000000u) ? ~u : (u | 0x80000000u);
}
__device__ __forceinline__ float unokey(unsigned int k) {
    return __uint_as_float((k & 0x80000000u) ? (k ^ 0x80000000u) : ~k);
}

// ============ K1: cp.async-staged; 8 lanes per row; histogram + threshold ==========
__global__ void __launch_bounds__(K1_BLK)
k_rowscore(const float* __restrict__ logits) {
    __shared__ float sbuf[2][STG_F];
    const int img = blockIdx.y;
    const int tid = threadIdx.x;
    const int lane = tid & 31;
    const int warp = tid >> 5;                       // 0..15
    const int sub = lane & 7;                        // element phase within row
    const int g = lane >> 3;                         // row within warp group (0..3)
    const int rows_blk = NP / K1_GX;                 // 2048
    const int nstg = rows_blk / ROWS_STG;            // 32
    const float* gsrc = logits + (size_t)img * NP * NC + (size_t)blockIdx.x * rows_blk * NC;

    auto stage_load = [&](int s, int buf) {
        const float4* src = (const float4*)(gsrc + (size_t)s * STG_F);
        unsigned int dst = (unsigned int)__cvta_generic_to_shared(&sbuf[buf][0]);
#pragma unroll
        for (int k = 0; k < 3; k++) {
            int idx = tid + k * K1_BLK;
            if (idx < STG_V)
                asm volatile("cp.async.cg.shared.global [%0], [%1], 16;\n"
                             :: "r"(dst + idx * 16), "l"(src + idx));
        }
        asm volatile("cp.async.commit_group;\n" ::);
    };

    stage_load(0, 0);
    stage_load(1, 1);

    for (int s = 0; s < nstg; s++) {
        asm volatile("cp.async.wait_group 1;\n" ::);
        __syncthreads();
        const int r = warp * 4 + g;                  // row within stage
        const float* row = &sbuf[s & 1][r * NC];
        float sum = 0.0f;
        float fg = -1e30f;
#pragma unroll
        for (int k = 0; k < 11; k++) {
            int e = sub + 8 * k;
            if (e < NC) {
                float v = row[e];
                sum += __expf(v);
                if (e > 0) fg = fmaxf(fg, v);        // exclude background col 0
            }
        }
        // reduce within each 8-lane group (handles all 4 rows at once)
#pragma unroll
        for (int o = 4; o; o >>= 1) {
            sum += __shfl_xor_sync(0xffffffffu, sum, o);
            fg = fmaxf(fg, __shfl_xor_sync(0xffffffffu, fg, o));
        }
        if (sub == 0) {
            float rs = fg - __logf(sum);
            int p = blockIdx.x * rows_blk + s * ROWS_STG + r;
            g_rowsc[img * NP + p] = rs;
            atomicAdd(&g_hist[img * NBINS + binf(rs)], 1u);
        }
        __syncthreads();
        if (s + 2 < nstg) stage_load(s + 2, s & 1);
        else asm volatile("cp.async.commit_group;\n" ::);
    }

    // ---- last-block-per-image: threshold find + hist re-zero ----
    __shared__ int slast;
    __shared__ unsigned int wsum[16];
    __shared__ int sbt;
    __syncthreads();
    __threadfence();
    if (tid == 0)
        slast = (atomicAdd(&g_done1[img], 1u) == gridDim.x - 1);
    __syncthreads();
    if (!slast) return;
    __threadfence();

    const int hi = NBINS - 1 - 4 * tid;               // 4 descending bins per thread
    unsigned int v[4];
    unsigned int sum = 0;
#pragma unroll
    for (int k = 0; k < 4; k++) {
        v[k] = g_hist[img * NBINS + hi - k];
        g_hist[img * NBINS + hi - k] = 0u;
        sum += v[k];
    }
    unsigned int x = sum;
#pragma unroll
    for (int o = 1; o < 32; o <<= 1) {
        unsigned int y = __shfl_up_sync(0xffffffffu, x, o);
        if (lane >= o) x += y;
    }
    if (lane == 31) wsum[warp] = x;
    __syncthreads();
    if (warp == 0) {
        unsigned int tv = (lane < 16) ? wsum[lane] : 0u;
        unsigned int tx = tv;
#pragma unroll
        for (int o = 1; o < 16; o <<= 1) {
            unsigned int y = __shfl_up_sync(0xffffffffu, tx, o);
            if (lane >= o) tx += y;
        }
        if (lane < 16) wsum[lane] = tx - tv;
    }
    __syncthreads();
    {
        unsigned int incl = x + wsum[warp];
        unsigned int excl = incl - sum;
        if (excl < NCAND && incl >= NCAND) {
            unsigned int cum = excl;
#pragma unroll
            for (int k = 0; k < 4; k++) {
                cum += v[k];
                if (cum >= NCAND) { sbt = hi - k; break; }
            }
        }
        if (tid == K1_BLK - 1 && incl < NCAND) sbt = 0;
    }
    __syncthreads();
    if (tid == 0) {
        int be = sbt - 1; if (be < 0) be = 0;
        int br = sbt - 2; if (br < 0) br = 0;
        g_bte[img] = be;
        g_btr[img] = br;
        g_done1[img] = 0u;
    }
}

// ============ K2: gather qualifying rows + exact rescore -> g_cand ==========
__global__ void __launch_bounds__(256)
k_gather(const float* __restrict__ logits) {
    __shared__ int rows[320];
    __shared__ int snr;
    const int img = blockIdx.y;
    const int tid = threadIdx.x;
    const int lane = tid & 31;
    const int warp = tid >> 5;
    const int btr = g_btr[img];
    const int bte = g_bte[img];

    if (tid == 0) snr = 0;
    __syncthreads();

    // scan this block's 1024 rows of approx scores (1 float4/thread)
    {
        const float4* rsc4 = (const float4*)(g_rowsc + (size_t)img * NP) + blockIdx.x * 256;
        float4 v = rsc4[tid];
        int br = blockIdx.x * 1024 + tid * 4;
        if (binf(v.x) >= btr) { int q = atomicAdd(&snr, 1); if (q < 320) rows[q] = br; }
        if (binf(v.y) >= btr) { int q = atomicAdd(&snr, 1); if (q < 320) rows[q] = br + 1; }
        if (binf(v.z) >= btr) { int q = atomicAdd(&snr, 1); if (q < 320) rows[q] = br + 2; }
        if (binf(v.w) >= btr) { int q = atomicAdd(&snr, 1); if (q < 320) rows[q] = br + 3; }
    }
    __syncthreads();

    int n = snr < 320 ? snr : 320;
    for (int ri = warp; ri < n; ri += 8) {
        int p = rows[ri];
        const float* row = logits + ((size_t)img * NP + p) * NC;
        float a = row[lane];
        float b = row[lane + 32];
        float c = (lane < 17) ? row[lane + 64] : -INFINITY;
        float m = fmaxf(fmaxf(a, b), c);
#pragma unroll
        for (int o = 16; o; o >>= 1) m = fmaxf(m, __shfl_xor_sync(0xffffffffu, m, o));
        float sv = expf(a - m) + expf(b - m);
        if (lane < 17) sv += expf(c - m);
#pragma unroll
        for (int o = 16; o; o >>= 1) sv += __shfl_xor_sync(0xffffffffu, sv, o);
        float logs = logf(sv);
#pragma unroll
        for (int k = 0; k < 3; k++) {
            int cc = lane + 32 * k;
            float xv = (k == 0) ? a : (k == 1) ? b : c;
            if (cc >= 1 && cc < NC) {
                float scv = (xv - m) - logs;
                if (binf(scv) >= bte) {
                    int pos = atomicAdd(&g_cnt[img], 1);
                    if (pos < SCAP) {
                        unsigned int flat = (unsigned int)(p * CM1 + (cc - 1));
                        g_cand[img * SCAP + pos] =
                            ((unsigned long long)okey(scv) << 32) | (unsigned int)(~flat);
                    }
                }
            }
        }
    }
}

// ============ K3: sort + decode + bitmask NMS + output (16 blocks) ==========
struct FinalS {
    unsigned long long cand[SCAP];     // 32 KB
    float4 obx4[NCAND];
    float bx[NCAND][4];
    float sc[NCAND];
    int   lb[NCAND];
    float area[NCAND];
    unsigned int adj[NCAND][13];
    unsigned int keepw[13];
    int   wpre[14];
    int   kidx[NOUT];
    float red[33];
};

__global__ void __launch_bounds__(1024, 1)
k_final(const float* __restrict__ bbox,
        const float* __restrict__ priors,
        float* __restrict__ out) {
    extern __shared__ char smraw[];
    FinalS& S = *reinterpret_cast<FinalS*>(smraw);
    const int img = blockIdx.x;
    const int tid = threadIdx.x;
    const int lane = tid & 31;
    const int warp = tid >> 5;

    int n = g_cnt[img];
    if (n > SCAP) n = SCAP;
    for (int i = tid; i < n; i += 1024) S.cand[i] = g_cand[img * SCAP + i];
    int M = 512;
    while (M < n) M <<= 1;
    for (int i = tid; i < M; i += 1024)
        if (i >= n) S.cand[i] = 0ull;
    __syncthreads();

    // bitonic sort descending on packed (key, ~idx)
    for (int k = 2; k <= M; k <<= 1) {
        for (int j = k >> 1; j > 0; j >>= 1) {
            for (int i = tid; i < M; i += 1024) {
                int ixj = i ^ j;
                if (ixj > i) {
                    unsigned long long a = S.cand[i], b = S.cand[ixj];
                    bool sw = ((i & k) == 0) ? (a < b) : (a > b);
                    if (sw) { S.cand[i] = b; S.cand[ixj] = a; }
                }
            }
            __syncthreads();
        }
    }

    // top-400 unpack + box decode
    if (tid < NCAND) {
        int r = tid;
        unsigned long long v = S.cand[r];
        float score = unokey((unsigned int)(v >> 32));
        int flat = (int)(~(unsigned int)(v & 0xffffffffu));
        int p = flat / CM1;
        int lbl = flat - p * CM1 + 1;
        const float* loc = bbox + ((size_t)img * NP + p) * 4;
        float px = priors[p * 4 + 0], py = priors[p * 4 + 1];
        float pw = priors[p * 4 + 2], ph = priors[p * 4 + 3];
        float cx = loc[0] * 0.1f * pw + px;
        float cy = loc[1] * 0.1f * ph + py;
        float w = expf(loc[2] * 0.2f) * pw;
        float h = expf(loc[3] * 0.2f) * ph;
        S.bx[r][0] = (cx - w * 0.5f) * 512.0f;
        S.bx[r][1] = (cy - h * 0.5f) * 512.0f;
        S.bx[r][2] = (cx + w * 0.5f) * 512.0f;
        S.bx[r][3] = (cy + h * 0.5f) * 512.0f;
        S.sc[r] = score;
        S.lb[r] = lbl;
    }
    __syncthreads();

    // max over all coords: two-level warp reduce
    {
        float mx = -INFINITY;
        for (int i = tid; i < NCAND * 4; i += 1024) mx = fmaxf(mx, ((float*)S.bx)[i]);
#pragma unroll
        for (int o = 16; o; o >>= 1) mx = fmaxf(mx, __shfl_xor_sync(0xffffffffu, mx, o));
        if (lane == 0) S.red[warp] = mx;
        __syncthreads();
        if (warp == 0) {
            float v = S.red[lane];
#pragma unroll
            for (int o = 16; o; o >>= 1) v = fmaxf(v, __shfl_xor_sync(0xffffffffu, v, o));
            if (lane == 0) S.red[32] = v;
        }
        __syncthreads();
    }
    float maxc = S.red[32];

    // class-offset boxes + areas (on offset boxes, matching reference rounding)
    if (tid < NCAND) {
        int r = tid;
        float off = (float)S.lb[r] * (maxc + 1.0f);
        float x1 = S.bx[r][0] + off, y1 = S.bx[r][1] + off;
        float x2 = S.bx[r][2] + off, y2 = S.bx[r][3] + off;
        S.obx4[r] = make_float4(x1, y1, x2, y2);
        S.area[r] = (x2 - x1) * (y2 - y1);
    }
    __syncthreads();

    // adjacency bitmatrix, words w >= i>>5 only
    for (int i = warp; i < NCAND; i += 32) {
        float4 bi = S.obx4[i];
        float ai = S.area[i];
        for (int w = i >> 5; w < 13; w++) {
            int j = w * 32 + lane;
            bool pred = false;
            if (j < NCAND && j > i) {
                float4 bj = S.obx4[j];
                float lt0 = fmaxf(bi.x, bj.x);
                float lt1 = fmaxf(bi.y, bj.y);
                float rb0 = fminf(bi.z, bj.z);
                float rb1 = fminf(bi.w, bj.w);
                float ww = fmaxf(rb0 - lt0, 0.0f);
                float hh = fmaxf(rb1 - lt1, 0.0f);
                float inter = ww * hh;
                float uni = ai + S.area[j] - inter;
                pred = (inter / fmaxf(uni, 1e-12f)) > 0.45f;
            }
            unsigned int bits = __ballot_sync(0xffffffffu, pred);
            if (lane == 0) S.adj[i][w] = bits;
        }
    }
    __syncthreads();

    // greedy NMS on warp 0 (13 keep-words, prefetched rows)
    if (tid < 32) {
        unsigned int kw;
        if (lane < 12) kw = 0xffffffffu;
        else if (lane == 12) kw = 0x0000ffffu;
        else kw = 0u;
        unsigned int nextrow = (lane < 13) ? S.adj[0][lane] : 0u;
        for (int i = 0; i < NCAND; i++) {
            unsigned int row = nextrow;
            nextrow = (lane < 13 && lane >= ((i + 1) >> 5) && i + 1 < NCAND)
                          ? S.adj[i + 1][lane] : 0u;
            unsigned int w = __shfl_sync(0xffffffffu, kw, i >> 5);
            if ((w >> (i & 31)) & 1u) kw &= ~row;
        }
        if (lane < 13) S.keepw[lane] = kw;
    }
    __syncthreads();

    // parallel rank select + output
    if (tid == 0) {
        int sacc = 0;
#pragma unroll
        for (int w = 0; w < 13; w++) { S.wpre[w] = sacc; sacc += __popc(S.keepw[w]); }
        S.wpre[13] = sacc;
    }
    __syncthreads();
    int K = S.wpre[13];
    if (tid < NCAND) {
        int i = tid;
        unsigned int word = S.keepw[i >> 5];
        unsigned int below = word & ((1u << (i & 31)) - 1u);
        int kb = S.wpre[i >> 5] + __popc(below);
        if ((word >> (i & 31)) & 1u) {
            if (kb < NOUT) S.kidx[kb] = i;
        } else {
            int nr2 = i - kb;
            if (K + nr2 < NOUT) S.kidx[K + nr2] = i;
        }
    }
    __syncthreads();

    if (tid < NOUT) {
        int r = tid;
        int i = S.kidx[r];
        bool kept = (S.keepw[i >> 5] >> (i & 31)) & 1u;
        float* ob = out + ((size_t)img * NOUT + r) * 4;
        ob[0] = S.bx[i][0]; ob[1] = S.bx[i][1]; ob[2] = S.bx[i][2]; ob[3] = S.bx[i][3];
        out[NB * NOUT * 4 + img * NOUT + r] = (float)S.lb[i];
        out[NB * NOUT * 5 + img * NOUT + r] = kept ? S.sc[i] : -INFINITY;
    }
    if (tid == 0) g_cnt[img] = 0;        // reset for next graph replay
}

// ---------------- launch ----------------
extern "C" void kernel_launch(void* const* d_in, const int* in_sizes, int n_in,
                              void* d_out, int out_size) {
    const float* logits = (const float*)d_in[0];
    const float* bbox   = (const float*)d_in[1];
    const float* priors = (const float*)d_in[2];
    float* out = (float*)d_out;

    k_rowscore<<<dim3(K1_GX, NB), K1_BLK>>>(logits);
    k_gather<<<dim3(32, NB), 256>>>(logits);
    cudaFuncSetAttribute(k_final, cudaFuncAttributeMaxDynamicSharedMemorySize,
                         (int)sizeof(FinalS));
    k_final<<<NB, 1024, sizeof(FinalS)>>>(bbox, priors, out);
}

// round 11
// speedup vs baseline: 1.3904x; 1.0653x over previous
#include <cuda_runtime.h>
#include <math.h>

#define NB    16
#define NP    32768
#define NC    81
#define CM1   80
#define NBINS 2048
#define SCAP  4096
#define NCAND 400
#define NOUT  100

#define K1_BLK   512
#define K1_GX    32
#define ROWS_STG 64
#define STG_F    (ROWS_STG * NC)        // 5184 floats per stage
#define STG_V    (STG_F / 4)            // 1296 float4 per stage

// ---------------- scratch (static device globals; zero-initialized at load) --------
__device__ float              g_rowsc[NB * NP];
__device__ unsigned int       g_hist[NB * NBINS];   // zeroed in-kernel after use
__device__ int                g_btr[NB];            // row filter bin   (sbt-2)
__device__ int                g_bte[NB];            // element filter bin (sbt-1)
__device__ int                g_cnt[NB];            // reset by K3
__device__ unsigned int       g_done1[NB];
__device__ unsigned long long g_cand[NB * SCAP];

__device__ __forceinline__ int binf(float s) {
    int b = (int)floorf((s + 30.0f) * (NBINS / 40.0f));
    b = b < 0 ? 0 : b;
    b = b > (NBINS - 1) ? (NBINS - 1) : b;
    return b;
}
__device__ __forceinline__ unsigned int okey(float s) {
    unsigned int u = __float_as_uint(s);
    return (u & 0x80000000u) ? ~u : (u | 0x80000000u);
}
__device__ __forceinline__ float unokey(unsigned int k) {
    return __uint_as_float((k & 0x80000000u) ? (k ^ 0x80000000u) : ~k);
}

// ============ K1: cp.async-staged; 8 lanes per row; histogram + threshold ==========
__global__ void __launch_bounds__(K1_BLK)
k_rowscore(const float* __restrict__ logits) {
    __shared__ float sbuf[2][STG_F];
    const int img = blockIdx.y;
    const int tid = threadIdx.x;
    const int lane = tid & 31;
    const int warp = tid >> 5;                       // 0..15
    const int sub = lane & 7;                        // element phase within row
    const int g = lane >> 3;                         // row within warp group (0..3)
    const int rows_blk = NP / K1_GX;                 // 1024
    const int nstg = rows_blk / ROWS_STG;            // 16
    const float* gsrc = logits + (size_t)img * NP * NC + (size_t)blockIdx.x * rows_blk * NC;

    auto stage_load = [&](int s, int buf) {
        const float4* src = (const float4*)(gsrc + (size_t)s * STG_F);
        unsigned int dst = (unsigned int)__cvta_generic_to_shared(&sbuf[buf][0]);
#pragma unroll
        for (int k = 0; k < 3; k++) {
            int idx = tid + k * K1_BLK;
            if (idx < STG_V)
                asm volatile("cp.async.cg.shared.global [%0], [%1], 16;\n"
                             :: "r"(dst + idx * 16), "l"(src + idx));
        }
        asm volatile("cp.async.commit_group;\n" ::);
    };

    stage_load(0, 0);
    stage_load(1, 1);

    for (int s = 0; s < nstg; s++) {
        asm volatile("cp.async.wait_group 1;\n" ::);
        __syncthreads();
        const int r = warp * 4 + g;                  // row within stage
        const float* row = &sbuf[s & 1][r * NC];
        float sum = 0.0f;
        float fg = -1e30f;
#pragma unroll
        for (int k = 0; k < 11; k++) {
            int e = sub + 8 * k;
            if (e < NC) {
                float v = row[e];
                sum += __expf(v);
                if (e > 0) fg = fmaxf(fg, v);        // exclude background col 0
            }
        }
#pragma unroll
        for (int o = 4; o; o >>= 1) {
            sum += __shfl_xor_sync(0xffffffffu, sum, o);
            fg = fmaxf(fg, __shfl_xor_sync(0xffffffffu, fg, o));
        }
        if (sub == 0) {
            float rs = fg - __logf(sum);
            int p = blockIdx.x * rows_blk + s * ROWS_STG + r;
            g_rowsc[img * NP + p] = rs;
            atomicAdd(&g_hist[img * NBINS + binf(rs)], 1u);
        }
        __syncthreads();
        if (s + 2 < nstg) stage_load(s + 2, s & 1);
        else asm volatile("cp.async.commit_group;\n" ::);
    }

    // ---- last-block-per-image: threshold find + hist re-zero ----
    __shared__ int slast;
    __shared__ unsigned int wsum[16];
    __shared__ int sbt;
    __syncthreads();
    __threadfence();
    if (tid == 0)
        slast = (atomicAdd(&g_done1[img], 1u) == gridDim.x - 1);
    __syncthreads();
    if (!slast) return;
    __threadfence();

    const int hi = NBINS - 1 - 4 * tid;               // 4 descending bins per thread
    unsigned int v[4];
    unsigned int sum = 0;
#pragma unroll
    for (int k = 0; k < 4; k++) {
        v[k] = g_hist[img * NBINS + hi - k];
        g_hist[img * NBINS + hi - k] = 0u;
        sum += v[k];
    }
    unsigned int x = sum;
#pragma unroll
    for (int o = 1; o < 32; o <<= 1) {
        unsigned int y = __shfl_up_sync(0xffffffffu, x, o);
        if (lane >= o) x += y;
    }
    if (lane == 31) wsum[warp] = x;
    __syncthreads();
    if (warp == 0) {
        unsigned int tv = (lane < 16) ? wsum[lane] : 0u;
        unsigned int tx = tv;
#pragma unroll
        for (int o = 1; o < 16; o <<= 1) {
            unsigned int y = __shfl_up_sync(0xffffffffu, tx, o);
            if (lane >= o) tx += y;
        }
        if (lane < 16) wsum[lane] = tx - tv;
    }
    __syncthreads();
    {
        unsigned int incl = x + wsum[warp];
        unsigned int excl = incl - sum;
        if (excl < NCAND && incl >= NCAND) {
            unsigned int cum = excl;
#pragma unroll
            for (int k = 0; k < 4; k++) {
                cum += v[k];
                if (cum >= NCAND) { sbt = hi - k; break; }
            }
        }
        if (tid == K1_BLK - 1 && incl < NCAND) sbt = 0;
    }
    __syncthreads();
    if (tid == 0) {
        int be = sbt - 1; if (be < 0) be = 0;
        int br = sbt - 2; if (br < 0) br = 0;
        g_bte[img] = be;
        g_btr[img] = br;
        g_done1[img] = 0u;
    }
}

// ============ K2: gather qualifying rows + exact rescore -> g_cand ==========
__global__ void __launch_bounds__(128)
k_gather(const float* __restrict__ logits) {
    __shared__ int rows[256];
    __shared__ int snr;
    const int img = blockIdx.y;
    const int tid = threadIdx.x;
    const int lane = tid & 31;
    const int warp = tid >> 5;
    const int btr = g_btr[img];
    const int bte = g_bte[img];

    if (tid == 0) snr = 0;
    __syncthreads();

    // scan this block's 512 rows of approx scores (1 float4/thread)
    {
        const float4* rsc4 = (const float4*)(g_rowsc + (size_t)img * NP) + blockIdx.x * 128;
        float4 v = rsc4[tid];
        int br = blockIdx.x * 512 + tid * 4;
        if (binf(v.x) >= btr) { int q = atomicAdd(&snr, 1); if (q < 256) rows[q] = br; }
        if (binf(v.y) >= btr) { int q = atomicAdd(&snr, 1); if (q < 256) rows[q] = br + 1; }
        if (binf(v.z) >= btr) { int q = atomicAdd(&snr, 1); if (q < 256) rows[q] = br + 2; }
        if (binf(v.w) >= btr) { int q = atomicAdd(&snr, 1); if (q < 256) rows[q] = br + 3; }
    }
    __syncthreads();

    int n = snr < 256 ? snr : 256;
    for (int ri = warp; ri < n; ri += 4) {
        int p = rows[ri];
        const float* row = logits + ((size_t)img * NP + p) * NC;
        float a = row[lane];
        float b = row[lane + 32];
        float c = (lane < 17) ? row[lane + 64] : -INFINITY;
        float m = fmaxf(fmaxf(a, b), c);
#pragma unroll
        for (int o = 16; o; o >>= 1) m = fmaxf(m, __shfl_xor_sync(0xffffffffu, m, o));
        float sv = expf(a - m) + expf(b - m);
        if (lane < 17) sv += expf(c - m);
#pragma unroll
        for (int o = 16; o; o >>= 1) sv += __shfl_xor_sync(0xffffffffu, sv, o);
        float logs = logf(sv);
#pragma unroll
        for (int k = 0; k < 3; k++) {
            int cc = lane + 32 * k;
            float xv = (k == 0) ? a : (k == 1) ? b : c;
            if (cc >= 1 && cc < NC) {
                float scv = (xv - m) - logs;
                if (binf(scv) >= bte) {
                    int pos = atomicAdd(&g_cnt[img], 1);
                    if (pos < SCAP) {
                        unsigned int flat = (unsigned int)(p * CM1 + (cc - 1));
                        g_cand[img * SCAP + pos] =
                            ((unsigned long long)okey(scv) << 32) | (unsigned int)(~flat);
                    }
                }
            }
        }
    }
}

// ============ K3: hybrid-bitonic sort + decode + bitmask NMS + output ==========
struct FinalS {
    unsigned long long cand[SCAP];     // 32 KB (exchange buffer / fallback sort)
    float4 obx4[NCAND];
    float bx[NCAND][4];
    float sc[NCAND];
    int   lb[NCAND];
    float area[NCAND];
    unsigned int adj[NCAND][13];
    unsigned int keepw[13];
    int   wpre[14];
    int   kidx[NOUT];
    float red[33];
};

__global__ void __launch_bounds__(1024, 1)
k_final(const float* __restrict__ bbox,
        const float* __restrict__ priors,
        float* __restrict__ out) {
    extern __shared__ char smraw[];
    FinalS& S = *reinterpret_cast<FinalS*>(smraw);
    const int img = blockIdx.x;
    const int tid = threadIdx.x;
    const int lane = tid & 31;
    const int warp = tid >> 5;

    int n = g_cnt[img];
    if (n > SCAP) n = SCAP;

    unsigned long long v400 = 0ull;      // sorted element at position tid (tid<400)

    if (n <= 1024) {
        // register-resident hybrid bitonic, fixed M=1024, descending, zeros sink
        unsigned long long val = (tid < n) ? g_cand[img * SCAP + tid] : 0ull;
#pragma unroll
        for (int k = 2; k <= 1024; k <<= 1) {
            for (int j = k >> 1; j >= 32; j >>= 1) {       // smem exchange passes
                S.cand[tid] = val;
                __syncthreads();
                unsigned long long other = S.cand[tid ^ j];
                __syncthreads();
                bool keep_max = ((tid & k) == 0) == ((tid & j) == 0);
                val = keep_max ? (val > other ? val : other)
                               : (val < other ? val : other);
            }
            int j0 = (k >> 1) < 16 ? (k >> 1) : 16;        // shfl passes (j<32)
            for (int j = j0; j >= 1; j >>= 1) {
                unsigned long long other = __shfl_xor_sync(0xffffffffu, val, j);
                bool keep_max = ((tid & k) == 0) == ((tid & j) == 0);
                val = keep_max ? (val > other ? val : other)
                               : (val < other ? val : other);
            }
        }
        v400 = val;
    } else {
        // fallback: in-smem bitonic over dynamic M (never expected)
        for (int i = tid; i < n; i += 1024) S.cand[i] = g_cand[img * SCAP + i];
        int M = 1024;
        while (M < n) M <<= 1;
        for (int i = tid; i < M; i += 1024)
            if (i >= n) S.cand[i] = 0ull;
        __syncthreads();
        for (int k = 2; k <= M; k <<= 1) {
            for (int j = k >> 1; j > 0; j >>= 1) {
                for (int i = tid; i < M; i += 1024) {
                    int ixj = i ^ j;
                    if (ixj > i) {
                        unsigned long long a = S.cand[i], b = S.cand[ixj];
                        bool sw = ((i & k) == 0) ? (a < b) : (a > b);
                        if (sw) { S.cand[i] = b; S.cand[ixj] = a; }
                    }
                }
                __syncthreads();
            }
        }
        if (tid < NCAND) v400 = S.cand[tid];
    }
    __syncthreads();

    // top-400 unpack + box decode (element tid of the sorted order is in v400)
    if (tid < NCAND) {
        int r = tid;
        unsigned long long v = v400;
        float score = unokey((unsigned int)(v >> 32));
        int flat = (int)(~(unsigned int)(v & 0xffffffffu));
        int p = flat / CM1;
        int lbl = flat - p * CM1 + 1;
        const float* loc = bbox + ((size_t)img * NP + p) * 4;
        float px = priors[p * 4 + 0], py = priors[p * 4 + 1];
        float pw = priors[p * 4 + 2], ph = priors[p * 4 + 3];
        float cx = loc[0] * 0.1f * pw + px;
        float cy = loc[1] * 0.1f * ph + py;
        float w = expf(loc[2] * 0.2f) * pw;
        float h = expf(loc[3] * 0.2f) * ph;
        S.bx[r][0] = (cx - w * 0.5f) * 512.0f;
        S.bx[r][1] = (cy - h * 0.5f) * 512.0f;
        S.bx[r][2] = (cx + w * 0.5f) * 512.0f;
        S.bx[r][3] = (cy + h * 0.5f) * 512.0f;
        S.sc[r] = score;
        S.lb[r] = lbl;
    }
    __syncthreads();

    // max over all coords: two-level warp reduce
    {
        float mx = -INFINITY;
        for (int i = tid; i < NCAND * 4; i += 1024) mx = fmaxf(mx, ((float*)S.bx)[i]);
#pragma unroll
        for (int o = 16; o; o >>= 1) mx = fmaxf(mx, __shfl_xor_sync(0xffffffffu, mx, o));
        if (lane == 0) S.red[warp] = mx;
        __syncthreads();
        if (warp == 0) {
            float v = S.red[lane];
#pragma unroll
            for (int o = 16; o; o >>= 1) v = fmaxf(v, __shfl_xor_sync(0xffffffffu, v, o));
            if (lane == 0) S.red[32] = v;
        }
        __syncthreads();
    }
    float maxc = S.red[32];

    // class-offset boxes + areas (on offset boxes, matching reference rounding)
    if (tid < NCAND) {
        int r = tid;
        float off = (float)S.lb[r] * (maxc + 1.0f);
        float x1 = S.bx[r][0] + off, y1 = S.bx[r][1] + off;
        float x2 = S.bx[r][2] + off, y2 = S.bx[r][3] + off;
        S.obx4[r] = make_float4(x1, y1, x2, y2);
        S.area[r] = (x2 - x1) * (y2 - y1);
    }
    __syncthreads();

    // adjacency bitmatrix, words w >= i>>5 only
    for (int i = warp; i < NCAND; i += 32) {
        float4 bi = S.obx4[i];
        float ai = S.area[i];
        for (int w = i >> 5; w < 13; w++) {
            int j = w * 32 + lane;
            bool pred = false;
            if (j < NCAND && j > i) {
                float4 bj = S.obx4[j];
                float lt0 = fmaxf(bi.x, bj.x);
                float lt1 = fmaxf(bi.y, bj.y);
                float rb0 = fminf(bi.z, bj.z);
                float rb1 = fminf(bi.w, bj.w);
                float ww = fmaxf(rb0 - lt0, 0.0f);
                float hh = fmaxf(rb1 - lt1, 0.0f);
                float inter = ww * hh;
                float uni = ai + S.area[j] - inter;
                pred = (inter / fmaxf(uni, 1e-12f)) > 0.45f;
            }
            unsigned int bits = __ballot_sync(0xffffffffu, pred);
            if (lane == 0) S.adj[i][w] = bits;
        }
    }
    __syncthreads();

    // greedy NMS on warp 0 (13 keep-words, prefetched rows)
    if (tid < 32) {
        unsigned int kw;
        if (lane < 12) kw = 0xffffffffu;
        else if (lane == 12) kw = 0x0000ffffu;
        else kw = 0u;
        unsigned int nextrow = (lane < 13) ? S.adj[0][lane] : 0u;
        for (int i = 0; i < NCAND; i++) {
            unsigned int row = nextrow;
            nextrow = (lane < 13 && lane >= ((i + 1) >> 5) && i + 1 < NCAND)
                          ? S.adj[i + 1][lane] : 0u;
            unsigned int w = __shfl_sync(0xffffffffu, kw, i >> 5);
            if ((w >> (i & 31)) & 1u) kw &= ~row;
        }
        if (lane < 13) S.keepw[lane] = kw;
    }
    __syncthreads();

    // parallel rank select + output
    if (tid == 0) {
        int sacc = 0;
#pragma unroll
        for (int w = 0; w < 13; w++) { S.wpre[w] = sacc; sacc += __popc(S.keepw[w]); }
        S.wpre[13] = sacc;
    }
    __syncthreads();
    int K = S.wpre[13];
    if (tid < NCAND) {
        int i = tid;
        unsigned int word = S.keepw[i >> 5];
        unsigned int below = word & ((1u << (i & 31)) - 1u);
        int kb = S.wpre[i >> 5] + __popc(below);
        if ((word >> (i & 31)) & 1u) {
            if (kb < NOUT) S.kidx[kb] = i;
        } else {
            int nr2 = i - kb;
            if (K + nr2 < NOUT) S.kidx[K + nr2] = i;
        }
    }
    __syncthreads();

    if (tid < NOUT) {
        int r = tid;
        int i = S.kidx[r];
        bool kept = (S.keepw[i >> 5] >> (i & 31)) & 1u;
        float* ob = out + ((size_t)img * NOUT + r) * 4;
        ob[0] = S.bx[i][0]; ob[1] = S.bx[i][1]; ob[2] = S.bx[i][2]; ob[3] = S.bx[i][3];
        out[NB * NOUT * 4 + img * NOUT + r] = (float)S.lb[i];
        out[NB * NOUT * 5 + img * NOUT + r] = kept ? S.sc[i] : -INFINITY;
    }
    if (tid == 0) g_cnt[img] = 0;        // reset for next graph replay
}

// ---------------- launch ----------------
extern "C" void kernel_launch(void* const* d_in, const int* in_sizes, int n_in,
                              void* d_out, int out_size) {
    const float* logits = (const float*)d_in[0];
    const float* bbox   = (const float*)d_in[1];
    const float* priors = (const float*)d_in[2];
    float* out = (float*)d_out;

    k_rowscore<<<dim3(K1_GX, NB), K1_BLK>>>(logits);
    k_gather<<<dim3(64, NB), 128>>>(logits);
    cudaFuncSetAttribute(k_final, cudaFuncAttributeMaxDynamicSharedMemorySize,
                         (int)sizeof(FinalS));
    k_final<<<NB, 1024, sizeof(FinalS)>>>(bbox, priors, out);
}